// round 1
// baseline (speedup 1.0000x reference)
#include <cuda_runtime.h>
#include <math.h>

#define Bn   16
#define Sn   512
#define Dn   2048
#define Hn   16
#define HDn  128
#define Mtot (Bn*Sn)      // 8192

// ---------------- scratch (alloc-free: __device__ globals) ----------------
__device__ float g_q[(size_t)Mtot * Dn];      // 64 MB
__device__ float g_k[(size_t)Mtot * Dn];      // 64 MB
__device__ float g_v[(size_t)Mtot * Dn];      // 64 MB
__device__ float g_attn[(size_t)Mtot * Dn];   // 64 MB
__device__ float g_p[(size_t)Bn * Hn * Sn * Sn]; // 256 MB (logits / probs)

// ============================================================================
// Generic 128x128x16 SGEMM, 256 threads, 8x8 per-thread register tile.
// C[M,N] = A[M,K] @ B[K,N] + bias, optional fused RoPE epilogue.
// A row-major lda=K, B row-major ldb=N, C row-major ldc=N.
// ============================================================================
template <int ROPE>
__global__ void __launch_bounds__(256)
proj_kernel(const float* __restrict__ A, const float* __restrict__ Bw,
            const float* __restrict__ bias, float* __restrict__ C,
            int M, int N, int K)
{
    __shared__ float As[16][132];   // [k][m], padded
    __shared__ float Bs[16][132];   // [k][n], padded

    const int tid = threadIdx.x;
    const int tx  = tid & 15;       // n direction
    const int ty  = tid >> 4;       // m direction
    const int rowStart = blockIdx.y * 128;
    const int colStart = blockIdx.x * 128;

    float acc[8][8];
    #pragma unroll
    for (int i = 0; i < 8; i++)
        #pragma unroll
        for (int j = 0; j < 8; j++) acc[i][j] = 0.f;

    for (int k0 = 0; k0 < K; k0 += 16) {
        // --- load A tile (128 x 16), transpose into As[k][m] ---
        #pragma unroll
        for (int it = 0; it < 2; ++it) {
            int f4  = tid + it * 256;     // 0..511
            int row = f4 >> 2;            // 0..127
            int kc4 = f4 & 3;             // 0..3
            float4 a = *(const float4*)&A[(size_t)(rowStart + row) * K + k0 + kc4 * 4];
            As[kc4*4+0][row] = a.x;
            As[kc4*4+1][row] = a.y;
            As[kc4*4+2][row] = a.z;
            As[kc4*4+3][row] = a.w;
        }
        // --- load B tile (16 x 128) into Bs[k][n] ---
        #pragma unroll
        for (int it = 0; it < 2; ++it) {
            int f4  = tid + it * 256;
            int kr  = f4 >> 5;            // 0..15
            int nc4 = f4 & 31;            // 0..31
            *(float4*)&Bs[kr][nc4 * 4] =
                *(const float4*)&Bw[(size_t)(k0 + kr) * N + colStart + nc4 * 4];
        }
        __syncthreads();

        #pragma unroll
        for (int kk = 0; kk < 16; ++kk) {
            float a0[8], b0[8];
            *(float4*)&a0[0] = *(float4*)&As[kk][ty * 8];
            *(float4*)&a0[4] = *(float4*)&As[kk][ty * 8 + 4];
            *(float4*)&b0[0] = *(float4*)&Bs[kk][tx * 8];
            *(float4*)&b0[4] = *(float4*)&Bs[kk][tx * 8 + 4];
            #pragma unroll
            for (int i = 0; i < 8; i++)
                #pragma unroll
                for (int j = 0; j < 8; j++)
                    acc[i][j] = fmaf(a0[i], b0[j], acc[i][j]);
        }
        __syncthreads();
    }

    // --- epilogue: bias (+ RoPE) ---
    const int cbase = colStart + tx * 8;
    float bv[8];
    *(float4*)&bv[0] = *(const float4*)&bias[cbase];
    *(float4*)&bv[4] = *(const float4*)&bias[cbase + 4];

    #pragma unroll
    for (int i = 0; i < 8; i++) {
        int m = rowStart + ty * 8 + i;
        float vals[8];
        #pragma unroll
        for (int j = 0; j < 8; j++) vals[j] = acc[i][j] + bv[j];
        if (ROPE) {
            int s = m & (Sn - 1);             // position
            #pragma unroll
            for (int j = 0; j < 8; j += 2) {
                int n    = cbase + j;
                int jh   = n & (HDn - 1);     // index within head
                int pidx = jh >> 1;           // pair index 0..63
                // inv_freq = 10000^(-2*pidx/128) = 2^(-pidx/64 * log2(1e4))
                float inv = exp2f((float)pidx * (-13.287712379549449f / 64.0f));
                float ang = (float)s * inv;
                float sn, cs;
                sincosf(ang, &sn, &cs);
                float e = vals[j], o = vals[j + 1];
                vals[j]     = e * cs - o * sn;
                vals[j + 1] = o * cs + e * sn;
            }
        }
        *(float4*)&C[(size_t)m * N + cbase]     = *(float4*)&vals[0];
        *(float4*)&C[(size_t)m * N + cbase + 4] = *(float4*)&vals[4];
    }
}

// ============================================================================
// Logits: P[bh, s, t] = scale * sum_d Q[b,s,h,d] * K[b,t,h,d], causal mask.
// NT GEMM per (b,h): M=512, N=512, K=128. Fully-masked tiles short-circuit.
// ============================================================================
__global__ void __launch_bounds__(256)
logits_kernel(const float* __restrict__ Q, const float* __restrict__ Kmat,
              float* __restrict__ P)
{
    const int bh = blockIdx.z;
    const int b  = bh >> 4, h = bh & 15;
    const int rowStart = blockIdx.y * 128;   // s
    const int colStart = blockIdx.x * 128;   // t

    const int tid = threadIdx.x;
    const int tx = tid & 15, ty = tid >> 4;
    float* Pout = P + (size_t)bh * Sn * Sn;

    if (colStart > rowStart) {
        // whole tile masked
        #pragma unroll
        for (int i = 0; i < 8; i++) {
            int s = rowStart + ty * 8 + i;
            float v[8];
            #pragma unroll
            for (int j = 0; j < 8; j++) v[j] = -1e9f;
            *(float4*)&Pout[(size_t)s * Sn + colStart + tx * 8]     = *(float4*)&v[0];
            *(float4*)&Pout[(size_t)s * Sn + colStart + tx * 8 + 4] = *(float4*)&v[4];
        }
        return;
    }

    const float* Qb = Q    + ((size_t)(b * Sn + rowStart) * Hn + h) * HDn; // row stride Dn
    const float* Kb = Kmat + ((size_t)(b * Sn + colStart) * Hn + h) * HDn;

    __shared__ float As[16][132];
    __shared__ float Bs[16][132];

    float acc[8][8];
    #pragma unroll
    for (int i = 0; i < 8; i++)
        #pragma unroll
        for (int j = 0; j < 8; j++) acc[i][j] = 0.f;

    for (int k0 = 0; k0 < HDn; k0 += 16) {
        #pragma unroll
        for (int it = 0; it < 2; ++it) {
            int f4  = tid + it * 256;
            int row = f4 >> 2;
            int kc4 = f4 & 3;
            float4 a = *(const float4*)&Qb[(size_t)row * Dn + k0 + kc4 * 4];
            As[kc4*4+0][row] = a.x; As[kc4*4+1][row] = a.y;
            As[kc4*4+2][row] = a.z; As[kc4*4+3][row] = a.w;
            float4 c = *(const float4*)&Kb[(size_t)row * Dn + k0 + kc4 * 4];
            Bs[kc4*4+0][row] = c.x; Bs[kc4*4+1][row] = c.y;
            Bs[kc4*4+2][row] = c.z; Bs[kc4*4+3][row] = c.w;
        }
        __syncthreads();
        #pragma unroll
        for (int kk = 0; kk < 16; ++kk) {
            float a0[8], b0[8];
            *(float4*)&a0[0] = *(float4*)&As[kk][ty * 8];
            *(float4*)&a0[4] = *(float4*)&As[kk][ty * 8 + 4];
            *(float4*)&b0[0] = *(float4*)&Bs[kk][tx * 8];
            *(float4*)&b0[4] = *(float4*)&Bs[kk][tx * 8 + 4];
            #pragma unroll
            for (int i = 0; i < 8; i++)
                #pragma unroll
                for (int j = 0; j < 8; j++)
                    acc[i][j] = fmaf(a0[i], b0[j], acc[i][j]);
        }
        __syncthreads();
    }

    const float scale = 0.08838834764831843f;   // 1/sqrt(128)
    #pragma unroll
    for (int i = 0; i < 8; i++) {
        int s = rowStart + ty * 8 + i;
        float v[8];
        #pragma unroll
        for (int j = 0; j < 8; j++) {
            int t = colStart + tx * 8 + j;
            v[j] = (t <= s) ? acc[i][j] * scale : -1e9f;
        }
        *(float4*)&Pout[(size_t)s * Sn + colStart + tx * 8]     = *(float4*)&v[0];
        *(float4*)&Pout[(size_t)s * Sn + colStart + tx * 8 + 4] = *(float4*)&v[4];
    }
}

// ============================================================================
// Row softmax over 512 elements. 1 block (128 threads) per row, in place.
// ============================================================================
__global__ void __launch_bounds__(128)
softmax_kernel(float* __restrict__ P)
{
    float* p = P + (size_t)blockIdx.x * Sn;
    const int tid = threadIdx.x;
    float4 v = ((float4*)p)[tid];

    float mx = fmaxf(fmaxf(v.x, v.y), fmaxf(v.z, v.w));
    #pragma unroll
    for (int o = 16; o; o >>= 1) mx = fmaxf(mx, __shfl_xor_sync(0xffffffffu, mx, o));
    __shared__ float red[4];
    if ((tid & 31) == 0) red[tid >> 5] = mx;
    __syncthreads();
    mx = fmaxf(fmaxf(red[0], red[1]), fmaxf(red[2], red[3]));

    float e0 = expf(v.x - mx), e1 = expf(v.y - mx);
    float e2 = expf(v.z - mx), e3 = expf(v.w - mx);
    float sm = e0 + e1 + e2 + e3;
    #pragma unroll
    for (int o = 16; o; o >>= 1) sm += __shfl_xor_sync(0xffffffffu, sm, o);
    __shared__ float red2[4];
    if ((tid & 31) == 0) red2[tid >> 5] = sm;
    __syncthreads();
    sm = red2[0] + red2[1] + red2[2] + red2[3];

    float inv = 1.0f / sm;
    float4 o4 = make_float4(e0 * inv, e1 * inv, e2 * inv, e3 * inv);
    ((float4*)p)[tid] = o4;
}

// ============================================================================
// O[b,s,h,:] = P[bh] @ V[b,:,h,:].  Per (b,h): M=512, N=128, K<=512 (causal).
// ============================================================================
__global__ void __launch_bounds__(256)
av_kernel(const float* __restrict__ P, const float* __restrict__ V,
          float* __restrict__ O)
{
    const int bh = blockIdx.z;
    const int b  = bh >> 4, h = bh & 15;
    const int rowStart = blockIdx.y * 128;  // s tile; N tile = full 128

    const int tid = threadIdx.x;
    const int tx = tid & 15, ty = tid >> 4;

    const float* Pb = P + (size_t)bh * Sn * Sn;
    const float* Vb = V + ((size_t)(b * Sn) * Hn + h) * HDn;   // t stride = Dn
    float*       Ob = O + ((size_t)(b * Sn + rowStart) * Hn + h) * HDn;

    __shared__ float As[16][132];
    __shared__ float Bs[16][132];

    float acc[8][8];
    #pragma unroll
    for (int i = 0; i < 8; i++)
        #pragma unroll
        for (int j = 0; j < 8; j++) acc[i][j] = 0.f;

    const int kmax = rowStart + 128;   // causal: P[s,t]=0 for t>s
    for (int k0 = 0; k0 < kmax; k0 += 16) {
        #pragma unroll
        for (int it = 0; it < 2; ++it) {
            int f4  = tid + it * 256;
            int row = f4 >> 2;
            int kc4 = f4 & 3;
            float4 a = *(const float4*)&Pb[(size_t)(rowStart + row) * Sn + k0 + kc4 * 4];
            As[kc4*4+0][row] = a.x; As[kc4*4+1][row] = a.y;
            As[kc4*4+2][row] = a.z; As[kc4*4+3][row] = a.w;
        }
        #pragma unroll
        for (int it = 0; it < 2; ++it) {
            int f4  = tid + it * 256;
            int kr  = f4 >> 5;
            int nc4 = f4 & 31;
            *(float4*)&Bs[kr][nc4 * 4] =
                *(const float4*)&Vb[(size_t)(k0 + kr) * Dn + nc4 * 4];
        }
        __syncthreads();
        #pragma unroll
        for (int kk = 0; kk < 16; ++kk) {
            float a0[8], b0[8];
            *(float4*)&a0[0] = *(float4*)&As[kk][ty * 8];
            *(float4*)&a0[4] = *(float4*)&As[kk][ty * 8 + 4];
            *(float4*)&b0[0] = *(float4*)&Bs[kk][tx * 8];
            *(float4*)&b0[4] = *(float4*)&Bs[kk][tx * 8 + 4];
            #pragma unroll
            for (int i = 0; i < 8; i++)
                #pragma unroll
                for (int j = 0; j < 8; j++)
                    acc[i][j] = fmaf(a0[i], b0[j], acc[i][j]);
        }
        __syncthreads();
    }

    #pragma unroll
    for (int i = 0; i < 8; i++) {
        float v[8];
        #pragma unroll
        for (int j = 0; j < 8; j++) v[j] = acc[i][j];
        float* dst = Ob + (size_t)(ty * 8 + i) * Dn + tx * 8;
        *(float4*)&dst[0] = *(float4*)&v[0];
        *(float4*)&dst[4] = *(float4*)&v[4];
    }
}

// ============================================================================
extern "C" void kernel_launch(void* const* d_in, const int* in_sizes, int n_in,
                              void* d_out, int out_size)
{
    const float* x  = (const float*)d_in[0];
    // d_in[1] = mask (causal, implicit — unused)
    const float* wq = (const float*)d_in[2];
    const float* bq = (const float*)d_in[3];
    const float* wk = (const float*)d_in[4];
    const float* bk = (const float*)d_in[5];
    const float* wv = (const float*)d_in[6];
    const float* bv = (const float*)d_in[7];
    const float* wo = (const float*)d_in[8];
    const float* bo = (const float*)d_in[9];
    float* out = (float*)d_out;

    float *qp, *kp, *vp, *ap, *pp;
    cudaGetSymbolAddress((void**)&qp, g_q);
    cudaGetSymbolAddress((void**)&kp, g_k);
    cudaGetSymbolAddress((void**)&vp, g_v);
    cudaGetSymbolAddress((void**)&ap, g_attn);
    cudaGetSymbolAddress((void**)&pp, g_p);

    dim3 blk(256);
    dim3 gproj(Dn / 128, Mtot / 128);          // (16, 64)

    proj_kernel<1><<<gproj, blk>>>(x, wq, bq, qp, Mtot, Dn, Dn);
    proj_kernel<1><<<gproj, blk>>>(x, wk, bk, kp, Mtot, Dn, Dn);
    proj_kernel<0><<<gproj, blk>>>(x, wv, bv, vp, Mtot, Dn, Dn);

    dim3 glog(Sn / 128, Sn / 128, Bn * Hn);    // (4, 4, 256)
    logits_kernel<<<glog, blk>>>(qp, kp, pp);

    softmax_kernel<<<Bn * Hn * Sn, 128>>>(pp);

    dim3 gav(1, Sn / 128, Bn * Hn);            // (1, 4, 256)
    av_kernel<<<gav, blk>>>(pp, vp, ap);

    proj_kernel<0><<<gproj, blk>>>(ap, wo, bo, out, Mtot, Dn, Dn);
}

// round 3
// speedup vs baseline: 2.4775x; 2.4775x over previous
#include <cuda_runtime.h>
#include <cuda_bf16.h>
#include <math.h>
#include <stdint.h>

#define Bn   16
#define Sn   512
#define Dn   2048
#define Hn   16
#define HDn  128
#define Mtot (Bn*Sn)      // 8192

// ---------------- scratch (alloc-free: __device__ globals) ----------------
__device__ float g_q[(size_t)Mtot * Dn];           // 64 MB
__device__ float g_k[(size_t)Mtot * Dn];           // 64 MB
__device__ float g_v[(size_t)Mtot * Dn];           // 64 MB
__device__ float g_attn[(size_t)Mtot * Dn];        // 64 MB
__device__ float g_p[(size_t)Bn * Hn * Sn * Sn];   // 256 MB
__device__ __nv_bfloat16 g_ahi[(size_t)Mtot * Dn]; // 32 MB
__device__ __nv_bfloat16 g_alo[(size_t)Mtot * Dn]; // 32 MB
__device__ __nv_bfloat16 g_whi[(size_t)Dn * Dn];   // 8 MB
__device__ __nv_bfloat16 g_wlo[(size_t)Dn * Dn];   // 8 MB

// ============================================================================
// PTX helpers (sm_80-compatible subset: HMMA / LDSM / LDGSTS only)
// ============================================================================
__device__ __forceinline__ uint32_t smem_u32(const void* p) {
    uint32_t a;
    asm("{ .reg .u64 t; cvta.to.shared.u64 t, %1; cvt.u32.u64 %0, t; }" : "=r"(a) : "l"(p));
    return a;
}
__device__ __forceinline__ void cp16(uint32_t saddr, const void* gptr) {
    asm volatile("cp.async.cg.shared.global [%0], [%1], 16;" :: "r"(saddr), "l"(gptr) : "memory");
}
__device__ __forceinline__ void cp_commit() {
    asm volatile("cp.async.commit_group;" ::: "memory");
}
template <int N>
__device__ __forceinline__ void cp_wait() {
    asm volatile("cp.async.wait_group %0;" :: "n"(N) : "memory");
}
__device__ __forceinline__ void ldsm4(uint32_t* r, uint32_t addr) {
    asm volatile("ldmatrix.sync.aligned.m8n8.x4.shared.b16 {%0,%1,%2,%3}, [%4];"
                 : "=r"(r[0]), "=r"(r[1]), "=r"(r[2]), "=r"(r[3]) : "r"(addr));
}
__device__ __forceinline__ void mma_bf16(float* d, const uint32_t* a, const uint32_t* b) {
    asm volatile("mma.sync.aligned.m16n8k16.row.col.f32.bf16.bf16.f32 "
                 "{%0,%1,%2,%3}, {%4,%5,%6,%7}, {%8,%9}, {%0,%1,%2,%3};"
                 : "+f"(d[0]), "+f"(d[1]), "+f"(d[2]), "+f"(d[3])
                 : "r"(a[0]), "r"(a[1]), "r"(a[2]), "r"(a[3]), "r"(b[0]), "r"(b[1]));
}

// ============================================================================
// Split / transpose preprocessing
// ============================================================================
__global__ void __launch_bounds__(256)
split_kernel(const float4* __restrict__ X, __nv_bfloat16* __restrict__ Hh,
             __nv_bfloat16* __restrict__ Hl)
{
    size_t i = (size_t)blockIdx.x * 256 + threadIdx.x;
    float4 v = X[i];
    float hx = __bfloat162float(__float2bfloat16(v.x));
    float hy = __bfloat162float(__float2bfloat16(v.y));
    float hz = __bfloat162float(__float2bfloat16(v.z));
    float hw = __bfloat162float(__float2bfloat16(v.w));
    __nv_bfloat162* H2 = (__nv_bfloat162*)Hh;
    __nv_bfloat162* L2 = (__nv_bfloat162*)Hl;
    H2[2*i]   = __floats2bfloat162_rn(hx, hy);
    H2[2*i+1] = __floats2bfloat162_rn(hz, hw);
    L2[2*i]   = __floats2bfloat162_rn(v.x - hx, v.y - hy);
    L2[2*i+1] = __floats2bfloat162_rn(v.z - hz, v.w - hw);
}

// W[k][n] fp32 -> Th/Tl[n][k] bf16 split (N x K row-major)
__global__ void __launch_bounds__(256)
splitT_kernel(const float* __restrict__ W, __nv_bfloat16* __restrict__ Th,
              __nv_bfloat16* __restrict__ Tl)
{
    __shared__ float t[32][33];
    int bx = blockIdx.x * 32;   // n
    int by = blockIdx.y * 32;   // k
    int tx = threadIdx.x, ty = threadIdx.y;
    #pragma unroll
    for (int i = 0; i < 32; i += 8)
        t[ty + i][tx] = W[(size_t)(by + ty + i) * Dn + bx + tx];
    __syncthreads();
    #pragma unroll
    for (int i = 0; i < 32; i += 8) {
        float v = t[tx][ty + i];
        float h = __bfloat162float(__float2bfloat16(v));
        size_t o = (size_t)(bx + ty + i) * Dn + by + tx;
        Th[o] = __float2bfloat16(h);
        Tl[o] = __float2bfloat16(v - h);
    }
}

// ============================================================================
// HMMA (mma.sync bf16) split-3 GEMM: C[M,2048] = A @ B^T (+bias, opt. RoPE)
// CTA 128x128, 8 warps (2x4), warp tile 64x32, K-chunk 32, cp.async 2-stage.
//
// SMEM tile layout: rows padded to 40 bf16 (80 B) -> ldmatrix conflict-free.
// ============================================================================
#define KC        32
#define ROWB      80                    // bytes per smem row (40 elems)
#define TILE_B    (128 * ROWB)          // 10240 bytes per tile
#define BUF_B     (4 * TILE_B)          // Ah,Al,Bh,Bl
#define GEMM_SMEM (2 * BUF_B)           // 81920

template <int ROPE>
__global__ void __launch_bounds__(256)
gemm_mma(const __nv_bfloat16* __restrict__ Ah, const __nv_bfloat16* __restrict__ Al,
         const __nv_bfloat16* __restrict__ Bh, const __nv_bfloat16* __restrict__ Bl,
         const float* __restrict__ bias, float* __restrict__ C)
{
    extern __shared__ char smem_raw[];
    const uint32_t sb = smem_u32(smem_raw);

    const int tid  = threadIdx.x;
    const int wid  = tid >> 5;
    const int lane = tid & 31;
    const int rowStart = blockIdx.y * 128;
    const int colStart = blockIdx.x * 128;
    const int warp_m = (wid & 1) * 64;
    const int warp_n = (wid >> 1) * 32;

    // ---- cp.async source/dest mapping (per thread: 2 segs per tile) ----
    // idx = tid + it*256 ; row = idx>>2 (0..127) ; seg = idx&3 (16B each)
    const __nv_bfloat16* gsrc[4] = {
        Ah + (size_t)rowStart * Dn, Al + (size_t)rowStart * Dn,
        Bh + (size_t)colStart * Dn, Bl + (size_t)colStart * Dn };

    // ---- ldmatrix lane offsets (bytes, within a tile) ----
    const uint32_t aoff = (uint32_t)((lane & 15) * ROWB + (lane >> 4) * 16);
    const uint32_t boff = (uint32_t)(((lane & 7) + ((lane >> 4) << 3)) * ROWB
                                     + ((lane >> 3) & 1) * 16);

    float acc[4][4][4];
    #pragma unroll
    for (int i = 0; i < 4; i++)
        #pragma unroll
        for (int j = 0; j < 4; j++)
            #pragma unroll
            for (int r = 0; r < 4; r++) acc[i][j][r] = 0.f;

    const int NCHUNK = Dn / KC;   // 64

    // ---- prefetch chunk 0 ----
    {
        const uint32_t bb = sb;
        #pragma unroll
        for (int t4 = 0; t4 < 4; ++t4)
            #pragma unroll
            for (int it = 0; it < 2; ++it) {
                int idx = tid + it * 256;
                int row = idx >> 2, seg = idx & 3;
                cp16(bb + t4 * TILE_B + row * ROWB + seg * 16,
                     (const char*)(gsrc[t4] + (size_t)row * Dn) + seg * 16);
            }
        cp_commit();
    }

    #pragma unroll 1
    for (int c = 0; c < NCHUNK; ++c) {
        if (c + 1 < NCHUNK) {
            const uint32_t bb = sb + ((c + 1) & 1) * BUF_B;
            const int k0 = (c + 1) * KC;
            #pragma unroll
            for (int t4 = 0; t4 < 4; ++t4)
                #pragma unroll
                for (int it = 0; it < 2; ++it) {
                    int idx = tid + it * 256;
                    int row = idx >> 2, seg = idx & 3;
                    cp16(bb + t4 * TILE_B + row * ROWB + seg * 16,
                         (const char*)(gsrc[t4] + (size_t)row * Dn + k0) + seg * 16);
                }
            cp_commit();
            cp_wait<1>();
        } else {
            cp_wait<0>();
        }
        __syncthreads();

        const uint32_t bb  = sb + (c & 1) * BUF_B;
        const uint32_t sAh = bb,             sAl = bb + TILE_B;
        const uint32_t sBh = bb + 2*TILE_B,  sBl = bb + 3*TILE_B;

        #pragma unroll
        for (int kk = 0; kk < 2; ++kk) {
            const uint32_t kb = (uint32_t)(kk * 32);   // 16 bf16 = 32 bytes
            uint32_t afrag[4][4], bfrag[4][2];

            // ---- pass 1: Ah x Bh ----
            #pragma unroll
            for (int i = 0; i < 4; ++i)
                ldsm4(afrag[i], sAh + aoff + kb + (uint32_t)((warp_m + i*16) * ROWB));
            #pragma unroll
            for (int p = 0; p < 2; ++p) {
                uint32_t r[4];
                ldsm4(r, sBh + boff + kb + (uint32_t)((warp_n + p*16) * ROWB));
                bfrag[p*2][0] = r[0]; bfrag[p*2][1] = r[1];
                bfrag[p*2+1][0] = r[2]; bfrag[p*2+1][1] = r[3];
            }
            #pragma unroll
            for (int i = 0; i < 4; ++i)
                #pragma unroll
                for (int j = 0; j < 4; ++j)
                    mma_bf16(acc[i][j], afrag[i], bfrag[j]);

            // ---- pass 2: Ah x Bl ----
            #pragma unroll
            for (int p = 0; p < 2; ++p) {
                uint32_t r[4];
                ldsm4(r, sBl + boff + kb + (uint32_t)((warp_n + p*16) * ROWB));
                bfrag[p*2][0] = r[0]; bfrag[p*2][1] = r[1];
                bfrag[p*2+1][0] = r[2]; bfrag[p*2+1][1] = r[3];
            }
            #pragma unroll
            for (int i = 0; i < 4; ++i)
                #pragma unroll
                for (int j = 0; j < 4; ++j)
                    mma_bf16(acc[i][j], afrag[i], bfrag[j]);

            // ---- pass 3: Al x Bh ----
            #pragma unroll
            for (int i = 0; i < 4; ++i)
                ldsm4(afrag[i], sAl + aoff + kb + (uint32_t)((warp_m + i*16) * ROWB));
            #pragma unroll
            for (int p = 0; p < 2; ++p) {
                uint32_t r[4];
                ldsm4(r, sBh + boff + kb + (uint32_t)((warp_n + p*16) * ROWB));
                bfrag[p*2][0] = r[0]; bfrag[p*2][1] = r[1];
                bfrag[p*2+1][0] = r[2]; bfrag[p*2+1][1] = r[3];
            }
            #pragma unroll
            for (int i = 0; i < 4; ++i)
                #pragma unroll
                for (int j = 0; j < 4; ++j)
                    mma_bf16(acc[i][j], afrag[i], bfrag[j]);
        }
        __syncthreads();
    }

    // ---- epilogue: bias (+ RoPE), direct global store ----
    #pragma unroll
    for (int i = 0; i < 4; ++i) {
        const int r0 = rowStart + warp_m + i * 16 + (lane >> 2);
        #pragma unroll
        for (int half = 0; half < 2; ++half) {
            const int r = r0 + half * 8;
            const int s = r & (Sn - 1);
            #pragma unroll
            for (int j = 0; j < 4; ++j) {
                const int c0 = colStart + warp_n + j * 8 + (lane & 3) * 2;
                float v0 = acc[i][j][half*2]   + bias[c0];
                float v1 = acc[i][j][half*2+1] + bias[c0 + 1];
                if (ROPE) {
                    int pidx = (c0 & (HDn - 1)) >> 1;
                    float inv = exp2f((float)pidx * (-13.287712379549449f / 64.0f));
                    float sn, cs;
                    sincosf((float)s * inv, &sn, &cs);
                    float e = v0, o = v1;
                    v0 = e * cs - o * sn;
                    v1 = o * cs + e * sn;
                }
                *(float2*)&C[(size_t)r * Dn + c0] = make_float2(v0, v1);
            }
        }
    }
}

// ============================================================================
// Attention (fp32, unchanged)
// ============================================================================
__global__ void __launch_bounds__(256)
logits_kernel(const float* __restrict__ Q, const float* __restrict__ Kmat,
              float* __restrict__ P)
{
    const int bh = blockIdx.z;
    const int b  = bh >> 4, h = bh & 15;
    const int rowStart = blockIdx.y * 128;
    const int colStart = blockIdx.x * 128;
    const int tid = threadIdx.x;
    const int tx = tid & 15, ty = tid >> 4;
    float* Pout = P + (size_t)bh * Sn * Sn;

    if (colStart > rowStart) {
        #pragma unroll
        for (int i = 0; i < 8; i++) {
            int s = rowStart + ty * 8 + i;
            float v[8];
            #pragma unroll
            for (int j = 0; j < 8; j++) v[j] = -1e9f;
            *(float4*)&Pout[(size_t)s * Sn + colStart + tx * 8]     = *(float4*)&v[0];
            *(float4*)&Pout[(size_t)s * Sn + colStart + tx * 8 + 4] = *(float4*)&v[4];
        }
        return;
    }

    const float* Qb = Q    + ((size_t)(b * Sn + rowStart) * Hn + h) * HDn;
    const float* Kb = Kmat + ((size_t)(b * Sn + colStart) * Hn + h) * HDn;

    __shared__ float As[16][132];
    __shared__ float Bs[16][132];

    float acc[8][8];
    #pragma unroll
    for (int i = 0; i < 8; i++)
        #pragma unroll
        for (int j = 0; j < 8; j++) acc[i][j] = 0.f;

    for (int k0 = 0; k0 < HDn; k0 += 16) {
        #pragma unroll
        for (int it = 0; it < 2; ++it) {
            int f4  = tid + it * 256;
            int row = f4 >> 2;
            int kc4 = f4 & 3;
            float4 a = *(const float4*)&Qb[(size_t)row * Dn + k0 + kc4 * 4];
            As[kc4*4+0][row] = a.x; As[kc4*4+1][row] = a.y;
            As[kc4*4+2][row] = a.z; As[kc4*4+3][row] = a.w;
            float4 c = *(const float4*)&Kb[(size_t)row * Dn + k0 + kc4 * 4];
            Bs[kc4*4+0][row] = c.x; Bs[kc4*4+1][row] = c.y;
            Bs[kc4*4+2][row] = c.z; Bs[kc4*4+3][row] = c.w;
        }
        __syncthreads();
        #pragma unroll
        for (int kk = 0; kk < 16; ++kk) {
            float a0[8], b0[8];
            *(float4*)&a0[0] = *(float4*)&As[kk][ty * 8];
            *(float4*)&a0[4] = *(float4*)&As[kk][ty * 8 + 4];
            *(float4*)&b0[0] = *(float4*)&Bs[kk][tx * 8];
            *(float4*)&b0[4] = *(float4*)&Bs[kk][tx * 8 + 4];
            #pragma unroll
            for (int i = 0; i < 8; i++)
                #pragma unroll
                for (int j = 0; j < 8; j++)
                    acc[i][j] = fmaf(a0[i], b0[j], acc[i][j]);
        }
        __syncthreads();
    }

    const float scale = 0.08838834764831843f;
    #pragma unroll
    for (int i = 0; i < 8; i++) {
        int s = rowStart + ty * 8 + i;
        float v[8];
        #pragma unroll
        for (int j = 0; j < 8; j++) {
            int t = colStart + tx * 8 + j;
            v[j] = (t <= s) ? acc[i][j] * scale : -1e9f;
        }
        *(float4*)&Pout[(size_t)s * Sn + colStart + tx * 8]     = *(float4*)&v[0];
        *(float4*)&Pout[(size_t)s * Sn + colStart + tx * 8 + 4] = *(float4*)&v[4];
    }
}

__global__ void __launch_bounds__(128)
softmax_kernel(float* __restrict__ P)
{
    float* p = P + (size_t)blockIdx.x * Sn;
    const int tid = threadIdx.x;
    float4 v = ((float4*)p)[tid];

    float mx = fmaxf(fmaxf(v.x, v.y), fmaxf(v.z, v.w));
    #pragma unroll
    for (int o = 16; o; o >>= 1) mx = fmaxf(mx, __shfl_xor_sync(0xffffffffu, mx, o));
    __shared__ float red[4];
    if ((tid & 31) == 0) red[tid >> 5] = mx;
    __syncthreads();
    mx = fmaxf(fmaxf(red[0], red[1]), fmaxf(red[2], red[3]));

    float e0 = expf(v.x - mx), e1 = expf(v.y - mx);
    float e2 = expf(v.z - mx), e3 = expf(v.w - mx);
    float sm = e0 + e1 + e2 + e3;
    #pragma unroll
    for (int o = 16; o; o >>= 1) sm += __shfl_xor_sync(0xffffffffu, sm, o);
    __shared__ float red2[4];
    if ((tid & 31) == 0) red2[tid >> 5] = sm;
    __syncthreads();
    sm = red2[0] + red2[1] + red2[2] + red2[3];

    float inv = 1.0f / sm;
    ((float4*)p)[tid] = make_float4(e0 * inv, e1 * inv, e2 * inv, e3 * inv);
}

__global__ void __launch_bounds__(256)
av_kernel(const float* __restrict__ P, const float* __restrict__ V,
          float* __restrict__ O)
{
    const int bh = blockIdx.z;
    const int b  = bh >> 4, h = bh & 15;
    const int rowStart = blockIdx.y * 128;
    const int tid = threadIdx.x;
    const int tx = tid & 15, ty = tid >> 4;

    const float* Pb = P + (size_t)bh * Sn * Sn;
    const float* Vb = V + ((size_t)(b * Sn) * Hn + h) * HDn;
    float*       Ob = O + ((size_t)(b * Sn + rowStart) * Hn + h) * HDn;

    __shared__ float As[16][132];
    __shared__ float Bs[16][132];

    float acc[8][8];
    #pragma unroll
    for (int i = 0; i < 8; i++)
        #pragma unroll
        for (int j = 0; j < 8; j++) acc[i][j] = 0.f;

    const int kmax = rowStart + 128;
    for (int k0 = 0; k0 < kmax; k0 += 16) {
        #pragma unroll
        for (int it = 0; it < 2; ++it) {
            int f4  = tid + it * 256;
            int row = f4 >> 2;
            int kc4 = f4 & 3;
            float4 a = *(const float4*)&Pb[(size_t)(rowStart + row) * Sn + k0 + kc4 * 4];
            As[kc4*4+0][row] = a.x; As[kc4*4+1][row] = a.y;
            As[kc4*4+2][row] = a.z; As[kc4*4+3][row] = a.w;
        }
        #pragma unroll
        for (int it = 0; it < 2; ++it) {
            int f4  = tid + it * 256;
            int kr  = f4 >> 5;
            int nc4 = f4 & 31;
            *(float4*)&Bs[kr][nc4 * 4] =
                *(const float4*)&Vb[(size_t)(k0 + kr) * Dn + nc4 * 4];
        }
        __syncthreads();
        #pragma unroll
        for (int kk = 0; kk < 16; ++kk) {
            float a0[8], b0[8];
            *(float4*)&a0[0] = *(float4*)&As[kk][ty * 8];
            *(float4*)&a0[4] = *(float4*)&As[kk][ty * 8 + 4];
            *(float4*)&b0[0] = *(float4*)&Bs[kk][tx * 8];
            *(float4*)&b0[4] = *(float4*)&Bs[kk][tx * 8 + 4];
            #pragma unroll
            for (int i = 0; i < 8; i++)
                #pragma unroll
                for (int j = 0; j < 8; j++)
                    acc[i][j] = fmaf(a0[i], b0[j], acc[i][j]);
        }
        __syncthreads();
    }

    #pragma unroll
    for (int i = 0; i < 8; i++) {
        float v[8];
        #pragma unroll
        for (int j = 0; j < 8; j++) v[j] = acc[i][j];
        float* dst = Ob + (size_t)(ty * 8 + i) * Dn + tx * 8;
        *(float4*)&dst[0] = *(float4*)&v[0];
        *(float4*)&dst[4] = *(float4*)&v[4];
    }
}

// ============================================================================
extern "C" void kernel_launch(void* const* d_in, const int* in_sizes, int n_in,
                              void* d_out, int out_size)
{
    const float* x  = (const float*)d_in[0];
    const float* wq = (const float*)d_in[2];
    const float* bq = (const float*)d_in[3];
    const float* wk = (const float*)d_in[4];
    const float* bk = (const float*)d_in[5];
    const float* wv = (const float*)d_in[6];
    const float* bv = (const float*)d_in[7];
    const float* wo = (const float*)d_in[8];
    const float* bo = (const float*)d_in[9];
    float* out = (float*)d_out;

    float *qp, *kp, *vp, *ap, *pp;
    __nv_bfloat16 *ahi, *alo, *whi, *wlo;
    cudaGetSymbolAddress((void**)&qp, g_q);
    cudaGetSymbolAddress((void**)&kp, g_k);
    cudaGetSymbolAddress((void**)&vp, g_v);
    cudaGetSymbolAddress((void**)&ap, g_attn);
    cudaGetSymbolAddress((void**)&pp, g_p);
    cudaGetSymbolAddress((void**)&ahi, g_ahi);
    cudaGetSymbolAddress((void**)&alo, g_alo);
    cudaGetSymbolAddress((void**)&whi, g_whi);
    cudaGetSymbolAddress((void**)&wlo, g_wlo);

    cudaFuncSetAttribute(gemm_mma<0>, cudaFuncAttributeMaxDynamicSharedMemorySize, GEMM_SMEM);
    cudaFuncSetAttribute(gemm_mma<1>, cudaFuncAttributeMaxDynamicSharedMemorySize, GEMM_SMEM);

    const int nSplitBlks = (int)(((size_t)Mtot * Dn / 4) / 256);
    dim3 gT(Dn / 32, Dn / 32), bT(32, 8);
    dim3 gG(Dn / 128, Mtot / 128);   // (16, 64)

    split_kernel<<<nSplitBlks, 256>>>((const float4*)x, ahi, alo);

    splitT_kernel<<<gT, bT>>>(wq, whi, wlo);
    gemm_mma<1><<<gG, 256, GEMM_SMEM>>>(ahi, alo, whi, wlo, bq, qp);

    splitT_kernel<<<gT, bT>>>(wk, whi, wlo);
    gemm_mma<1><<<gG, 256, GEMM_SMEM>>>(ahi, alo, whi, wlo, bk, kp);

    splitT_kernel<<<gT, bT>>>(wv, whi, wlo);
    gemm_mma<0><<<gG, 256, GEMM_SMEM>>>(ahi, alo, whi, wlo, bv, vp);

    dim3 glog(Sn / 128, Sn / 128, Bn * Hn);
    logits_kernel<<<glog, 256>>>(qp, kp, pp);
    softmax_kernel<<<Bn * Hn * Sn, 128>>>(pp);
    dim3 gav(1, Sn / 128, Bn * Hn);
    av_kernel<<<gav, 256>>>(pp, vp, ap);

    split_kernel<<<nSplitBlks, 256>>>((const float4*)ap, ahi, alo);
    splitT_kernel<<<gT, bT>>>(wo, whi, wlo);
    gemm_mma<0><<<gG, 256, GEMM_SMEM>>>(ahi, alo, whi, wlo, bo, out);
}

// round 4
// speedup vs baseline: 2.8427x; 1.1474x over previous
#include <cuda_runtime.h>
#include <cuda_bf16.h>
#include <math.h>
#include <stdint.h>

#define Bn   16
#define Sn   512
#define Dn   2048
#define Hn   16
#define HDn  128
#define Mtot (Bn*Sn)      // 8192

// ---------------- scratch (alloc-free: __device__ globals) ----------------
__device__ float g_p[(size_t)Bn * Hn * Sn * Sn];    // 256 MB logits (fp32)
__device__ __nv_bfloat16 g_ahi[(size_t)Mtot * Dn];  // 32 MB (x / attn-out hi)
__device__ __nv_bfloat16 g_alo[(size_t)Mtot * Dn];  // 32 MB
__device__ __nv_bfloat16 g_whi[(size_t)Dn * Dn];    // 8 MB (W^T hi)
__device__ __nv_bfloat16 g_wlo[(size_t)Dn * Dn];    // 8 MB
__device__ __nv_bfloat16 g_qh[(size_t)Mtot * Dn];   // 32 MB each
__device__ __nv_bfloat16 g_ql[(size_t)Mtot * Dn];
__device__ __nv_bfloat16 g_kh[(size_t)Mtot * Dn];
__device__ __nv_bfloat16 g_kl[(size_t)Mtot * Dn];
__device__ __nv_bfloat16 g_vh[(size_t)Mtot * Dn];
__device__ __nv_bfloat16 g_vl[(size_t)Mtot * Dn];
__device__ __nv_bfloat16 g_ph[(size_t)Bn * Hn * Sn * Sn];  // 128 MB probs hi
__device__ __nv_bfloat16 g_pl[(size_t)Bn * Hn * Sn * Sn];  // 128 MB probs lo

// ============================================================================
// PTX helpers (sm_80-compatible subset)
// ============================================================================
__device__ __forceinline__ uint32_t smem_u32(const void* p) {
    uint32_t a;
    asm("{ .reg .u64 t; cvta.to.shared.u64 t, %1; cvt.u32.u64 %0, t; }" : "=r"(a) : "l"(p));
    return a;
}
__device__ __forceinline__ void cp16(uint32_t saddr, const void* gptr) {
    asm volatile("cp.async.cg.shared.global [%0], [%1], 16;" :: "r"(saddr), "l"(gptr) : "memory");
}
__device__ __forceinline__ void cp_commit() {
    asm volatile("cp.async.commit_group;" ::: "memory");
}
template <int N>
__device__ __forceinline__ void cp_wait() {
    asm volatile("cp.async.wait_group %0;" :: "n"(N) : "memory");
}
__device__ __forceinline__ void ldsm4(uint32_t* r, uint32_t addr) {
    asm volatile("ldmatrix.sync.aligned.m8n8.x4.shared.b16 {%0,%1,%2,%3}, [%4];"
                 : "=r"(r[0]), "=r"(r[1]), "=r"(r[2]), "=r"(r[3]) : "r"(addr));
}
__device__ __forceinline__ void ldsm4t(uint32_t* r, uint32_t addr) {
    asm volatile("ldmatrix.sync.aligned.m8n8.x4.trans.shared.b16 {%0,%1,%2,%3}, [%4];"
                 : "=r"(r[0]), "=r"(r[1]), "=r"(r[2]), "=r"(r[3]) : "r"(addr));
}
__device__ __forceinline__ void mma_bf16(float* d, const uint32_t* a, const uint32_t* b) {
    asm volatile("mma.sync.aligned.m16n8k16.row.col.f32.bf16.bf16.f32 "
                 "{%0,%1,%2,%3}, {%4,%5,%6,%7}, {%8,%9}, {%0,%1,%2,%3};"
                 : "+f"(d[0]), "+f"(d[1]), "+f"(d[2]), "+f"(d[3])
                 : "r"(a[0]), "r"(a[1]), "r"(a[2]), "r"(a[3]), "r"(b[0]), "r"(b[1]));
}

// ============================================================================
// Tile geometry
// ============================================================================
#define KC     32
#define ROWB   80                    // bytes/row for 32-bf16 tiles (padded)
#define TILE_B (128 * ROWB)          // 10240 B
#define VROWB  272                   // bytes/row for 128-bf16 V tiles (padded)
#define VTILE_B (32 * VROWB)         // 8704 B

// rows=128, 4x16B segs per row; g pre-offset to (row0,k0); ldg in elements
__device__ __forceinline__ void load_tile(const __nv_bfloat16* __restrict__ g,
                                          int ldg, uint32_t sdst, int tid)
{
    #pragma unroll
    for (int it = 0; it < 2; ++it) {
        int idx = tid + it * 256;
        int row = idx >> 2, seg = idx & 3;
        cp16(sdst + (uint32_t)(row * ROWB + seg * 16),
             (const char*)(g + (size_t)row * ldg) + seg * 16);
    }
}
// rows=32, 16x16B segs per row (128 bf16); g pre-offset; stride Dn
__device__ __forceinline__ void load_vtile(const __nv_bfloat16* __restrict__ g,
                                           uint32_t sdst, int tid)
{
    #pragma unroll
    for (int it = 0; it < 2; ++it) {
        int idx = tid + it * 256;
        int row = idx >> 4, seg = idx & 15;
        cp16(sdst + (uint32_t)(row * VROWB + seg * 16),
             (const char*)(g + (size_t)row * Dn) + seg * 16);
    }
}

__device__ __forceinline__ void split_store(__nv_bfloat16* __restrict__ OH,
                                            __nv_bfloat16* __restrict__ OL,
                                            size_t off, float v0, float v1)
{
    __nv_bfloat16 h0 = __float2bfloat16(v0), h1 = __float2bfloat16(v1);
    __nv_bfloat16 l0 = __float2bfloat16(v0 - __bfloat162float(h0));
    __nv_bfloat16 l1 = __float2bfloat16(v1 - __bfloat162float(h1));
    *(__nv_bfloat162*)&OH[off] = __halves2bfloat162(h0, h1);
    *(__nv_bfloat162*)&OL[off] = __halves2bfloat162(l0, l1);
}

// ============================================================================
// Split / transpose preprocessing
// ============================================================================
__global__ void __launch_bounds__(256)
split_kernel(const float4* __restrict__ X, __nv_bfloat16* __restrict__ Hh,
             __nv_bfloat16* __restrict__ Hl)
{
    size_t i = (size_t)blockIdx.x * 256 + threadIdx.x;
    float4 v = X[i];
    float hx = __bfloat162float(__float2bfloat16(v.x));
    float hy = __bfloat162float(__float2bfloat16(v.y));
    float hz = __bfloat162float(__float2bfloat16(v.z));
    float hw = __bfloat162float(__float2bfloat16(v.w));
    __nv_bfloat162* H2 = (__nv_bfloat162*)Hh;
    __nv_bfloat162* L2 = (__nv_bfloat162*)Hl;
    H2[2*i]   = __floats2bfloat162_rn(hx, hy);
    H2[2*i+1] = __floats2bfloat162_rn(hz, hw);
    L2[2*i]   = __floats2bfloat162_rn(v.x - hx, v.y - hy);
    L2[2*i+1] = __floats2bfloat162_rn(v.z - hz, v.w - hw);
}

__global__ void __launch_bounds__(256)
splitT_kernel(const float* __restrict__ W, __nv_bfloat16* __restrict__ Th,
              __nv_bfloat16* __restrict__ Tl)
{
    __shared__ float t[32][33];
    int bx = blockIdx.x * 32;   // n
    int by = blockIdx.y * 32;   // k
    int tx = threadIdx.x, ty = threadIdx.y;
    #pragma unroll
    for (int i = 0; i < 32; i += 8)
        t[ty + i][tx] = W[(size_t)(by + ty + i) * Dn + bx + tx];
    __syncthreads();
    #pragma unroll
    for (int i = 0; i < 32; i += 8) {
        float v = t[tx][ty + i];
        float h = __bfloat162float(__float2bfloat16(v));
        size_t o = (size_t)(bx + ty + i) * Dn + by + tx;
        Th[o] = __float2bfloat16(h);
        Tl[o] = __float2bfloat16(v - h);
    }
}

// ============================================================================
// HMMA split-3 projection GEMM. EPI: 0 = bias->fp32, 1 = bias+RoPE->split,
// 2 = bias->split.
// ============================================================================
#define BUF_B     (4 * TILE_B)
#define GEMM_SMEM (2 * BUF_B)        // 81920

template <int EPI>
__global__ void __launch_bounds__(256)
gemm_mma(const __nv_bfloat16* __restrict__ Ah, const __nv_bfloat16* __restrict__ Al,
         const __nv_bfloat16* __restrict__ Bh, const __nv_bfloat16* __restrict__ Bl,
         const float* __restrict__ bias, float* __restrict__ Cf,
         __nv_bfloat16* __restrict__ Oh, __nv_bfloat16* __restrict__ Ol)
{
    extern __shared__ char smem_raw[];
    const uint32_t sb = smem_u32(smem_raw);

    const int tid  = threadIdx.x;
    const int wid  = tid >> 5;
    const int lane = tid & 31;
    const int rowStart = blockIdx.y * 128;
    const int colStart = blockIdx.x * 128;
    const int warp_m = (wid & 1) * 64;
    const int warp_n = (wid >> 1) * 32;

    const __nv_bfloat16* gA0 = Ah + (size_t)rowStart * Dn;
    const __nv_bfloat16* gA1 = Al + (size_t)rowStart * Dn;
    const __nv_bfloat16* gB0 = Bh + (size_t)colStart * Dn;
    const __nv_bfloat16* gB1 = Bl + (size_t)colStart * Dn;

    const uint32_t aoff = (uint32_t)((lane & 15) * ROWB + (lane >> 4) * 16);
    const uint32_t boff = (uint32_t)(((lane & 7) + ((lane >> 4) << 3)) * ROWB
                                     + ((lane >> 3) & 1) * 16);

    float acc[4][4][4];
    #pragma unroll
    for (int i = 0; i < 4; i++)
        #pragma unroll
        for (int j = 0; j < 4; j++)
            #pragma unroll
            for (int r = 0; r < 4; r++) acc[i][j][r] = 0.f;

    const int NCHUNK = Dn / KC;   // 64

    {
        const uint32_t bb = sb;
        load_tile(gA0, Dn, bb,            tid);
        load_tile(gA1, Dn, bb + TILE_B,   tid);
        load_tile(gB0, Dn, bb + 2*TILE_B, tid);
        load_tile(gB1, Dn, bb + 3*TILE_B, tid);
        cp_commit();
    }

    #pragma unroll 1
    for (int c = 0; c < NCHUNK; ++c) {
        if (c + 1 < NCHUNK) {
            const uint32_t bb = sb + ((c + 1) & 1) * BUF_B;
            const int k0 = (c + 1) * KC;
            load_tile(gA0 + k0, Dn, bb,            tid);
            load_tile(gA1 + k0, Dn, bb + TILE_B,   tid);
            load_tile(gB0 + k0, Dn, bb + 2*TILE_B, tid);
            load_tile(gB1 + k0, Dn, bb + 3*TILE_B, tid);
            cp_commit();
            cp_wait<1>();
        } else {
            cp_wait<0>();
        }
        __syncthreads();

        const uint32_t bb  = sb + (c & 1) * BUF_B;
        const uint32_t sAh = bb,             sAl = bb + TILE_B;
        const uint32_t sBh = bb + 2*TILE_B,  sBl = bb + 3*TILE_B;

        #pragma unroll
        for (int kk = 0; kk < 2; ++kk) {
            const uint32_t kb = (uint32_t)(kk * 32);
            uint32_t afrag[4][4], bfrag[4][2];

            #pragma unroll
            for (int i = 0; i < 4; ++i)
                ldsm4(afrag[i], sAh + aoff + kb + (uint32_t)((warp_m + i*16) * ROWB));
            #pragma unroll
            for (int p = 0; p < 2; ++p) {
                uint32_t r[4];
                ldsm4(r, sBh + boff + kb + (uint32_t)((warp_n + p*16) * ROWB));
                bfrag[p*2][0] = r[0]; bfrag[p*2][1] = r[1];
                bfrag[p*2+1][0] = r[2]; bfrag[p*2+1][1] = r[3];
            }
            #pragma unroll
            for (int i = 0; i < 4; ++i)
                #pragma unroll
                for (int j = 0; j < 4; ++j)
                    mma_bf16(acc[i][j], afrag[i], bfrag[j]);

            #pragma unroll
            for (int p = 0; p < 2; ++p) {
                uint32_t r[4];
                ldsm4(r, sBl + boff + kb + (uint32_t)((warp_n + p*16) * ROWB));
                bfrag[p*2][0] = r[0]; bfrag[p*2][1] = r[1];
                bfrag[p*2+1][0] = r[2]; bfrag[p*2+1][1] = r[3];
            }
            #pragma unroll
            for (int i = 0; i < 4; ++i)
                #pragma unroll
                for (int j = 0; j < 4; ++j)
                    mma_bf16(acc[i][j], afrag[i], bfrag[j]);

            #pragma unroll
            for (int i = 0; i < 4; ++i)
                ldsm4(afrag[i], sAl + aoff + kb + (uint32_t)((warp_m + i*16) * ROWB));
            #pragma unroll
            for (int p = 0; p < 2; ++p) {
                uint32_t r[4];
                ldsm4(r, sBh + boff + kb + (uint32_t)((warp_n + p*16) * ROWB));
                bfrag[p*2][0] = r[0]; bfrag[p*2][1] = r[1];
                bfrag[p*2+1][0] = r[2]; bfrag[p*2+1][1] = r[3];
            }
            #pragma unroll
            for (int i = 0; i < 4; ++i)
                #pragma unroll
                for (int j = 0; j < 4; ++j)
                    mma_bf16(acc[i][j], afrag[i], bfrag[j]);
        }
        __syncthreads();
    }

    // ---- epilogue ----
    #pragma unroll
    for (int i = 0; i < 4; ++i) {
        const int r0 = rowStart + warp_m + i * 16 + (lane >> 2);
        #pragma unroll
        for (int half = 0; half < 2; ++half) {
            const int r = r0 + half * 8;
            const int s = r & (Sn - 1);
            #pragma unroll
            for (int j = 0; j < 4; ++j) {
                const int c0 = colStart + warp_n + j * 8 + (lane & 3) * 2;
                float v0 = acc[i][j][half*2]   + bias[c0];
                float v1 = acc[i][j][half*2+1] + bias[c0 + 1];
                if (EPI == 1) {
                    int pidx = (c0 & (HDn - 1)) >> 1;
                    float inv = exp2f((float)pidx * (-13.287712379549449f / 64.0f));
                    float sn, cs;
                    sincosf((float)s * inv, &sn, &cs);
                    float e = v0, o = v1;
                    v0 = e * cs - o * sn;
                    v1 = o * cs + e * sn;
                }
                if (EPI == 0)
                    *(float2*)&Cf[(size_t)r * Dn + c0] = make_float2(v0, v1);
                else
                    split_store(Oh, Ol, (size_t)r * Dn + c0, v0, v1);
            }
        }
    }
}

// ============================================================================
// Logits HMMA: P[bh,s,t] = scale * (Qh+Ql)·(Kh+Kl) (split-3), fp32 out.
// No masking here — softmax masks by index. Upper tiles skipped.
// ============================================================================
#define LBUF_B     (4 * TILE_B)
#define LOGIT_SMEM (2 * LBUF_B)

__global__ void __launch_bounds__(256)
logits_mma(const __nv_bfloat16* __restrict__ Qh, const __nv_bfloat16* __restrict__ Ql,
           const __nv_bfloat16* __restrict__ Kh, const __nv_bfloat16* __restrict__ Kl,
           float* __restrict__ P)
{
    const int bh = blockIdx.z;
    const int rowStart = blockIdx.y * 128;   // s
    const int colStart = blockIdx.x * 128;   // t
    if (colStart > rowStart) return;

    extern __shared__ char smem_raw[];
    const uint32_t sb = smem_u32(smem_raw);

    const int b = bh >> 4, h = bh & 15;
    const int tid  = threadIdx.x;
    const int wid  = tid >> 5;
    const int lane = tid & 31;
    const int warp_m = (wid & 1) * 64;
    const int warp_n = (wid >> 1) * 32;

    const __nv_bfloat16* gQh = Qh + ((size_t)(b * Sn + rowStart) * Hn + h) * HDn;
    const __nv_bfloat16* gQl = Ql + ((size_t)(b * Sn + rowStart) * Hn + h) * HDn;
    const __nv_bfloat16* gKh = Kh + ((size_t)(b * Sn + colStart) * Hn + h) * HDn;
    const __nv_bfloat16* gKl = Kl + ((size_t)(b * Sn + colStart) * Hn + h) * HDn;

    const uint32_t aoff = (uint32_t)((lane & 15) * ROWB + (lane >> 4) * 16);
    const uint32_t boff = (uint32_t)(((lane & 7) + ((lane >> 4) << 3)) * ROWB
                                     + ((lane >> 3) & 1) * 16);

    float acc[4][4][4];
    #pragma unroll
    for (int i = 0; i < 4; i++)
        #pragma unroll
        for (int j = 0; j < 4; j++)
            #pragma unroll
            for (int r = 0; r < 4; r++) acc[i][j][r] = 0.f;

    {
        const uint32_t bb = sb;
        load_tile(gQh, Dn, bb,            tid);
        load_tile(gQl, Dn, bb + TILE_B,   tid);
        load_tile(gKh, Dn, bb + 2*TILE_B, tid);
        load_tile(gKl, Dn, bb + 3*TILE_B, tid);
        cp_commit();
    }

    #pragma unroll 1
    for (int c = 0; c < 4; ++c) {          // K = 128 = 4 chunks
        if (c + 1 < 4) {
            const uint32_t bb = sb + ((c + 1) & 1) * LBUF_B;
            const int k0 = (c + 1) * KC;
            load_tile(gQh + k0, Dn, bb,            tid);
            load_tile(gQl + k0, Dn, bb + TILE_B,   tid);
            load_tile(gKh + k0, Dn, bb + 2*TILE_B, tid);
            load_tile(gKl + k0, Dn, bb + 3*TILE_B, tid);
            cp_commit();
            cp_wait<1>();
        } else {
            cp_wait<0>();
        }
        __syncthreads();

        const uint32_t bb  = sb + (c & 1) * LBUF_B;
        const uint32_t sQh = bb,             sQl = bb + TILE_B;
        const uint32_t sKh = bb + 2*TILE_B,  sKl = bb + 3*TILE_B;

        #pragma unroll
        for (int kk = 0; kk < 2; ++kk) {
            const uint32_t kb = (uint32_t)(kk * 32);
            uint32_t afrag[4][4], bfrag[4][2];

            #pragma unroll
            for (int i = 0; i < 4; ++i)
                ldsm4(afrag[i], sQh + aoff + kb + (uint32_t)((warp_m + i*16) * ROWB));
            #pragma unroll
            for (int p = 0; p < 2; ++p) {
                uint32_t r[4];
                ldsm4(r, sKh + boff + kb + (uint32_t)((warp_n + p*16) * ROWB));
                bfrag[p*2][0] = r[0]; bfrag[p*2][1] = r[1];
                bfrag[p*2+1][0] = r[2]; bfrag[p*2+1][1] = r[3];
            }
            #pragma unroll
            for (int i = 0; i < 4; ++i)
                #pragma unroll
                for (int j = 0; j < 4; ++j)
                    mma_bf16(acc[i][j], afrag[i], bfrag[j]);

            #pragma unroll
            for (int p = 0; p < 2; ++p) {
                uint32_t r[4];
                ldsm4(r, sKl + boff + kb + (uint32_t)((warp_n + p*16) * ROWB));
                bfrag[p*2][0] = r[0]; bfrag[p*2][1] = r[1];
                bfrag[p*2+1][0] = r[2]; bfrag[p*2+1][1] = r[3];
            }
            #pragma unroll
            for (int i = 0; i < 4; ++i)
                #pragma unroll
                for (int j = 0; j < 4; ++j)
                    mma_bf16(acc[i][j], afrag[i], bfrag[j]);

            #pragma unroll
            for (int i = 0; i < 4; ++i)
                ldsm4(afrag[i], sQl + aoff + kb + (uint32_t)((warp_m + i*16) * ROWB));
            #pragma unroll
            for (int p = 0; p < 2; ++p) {
                uint32_t r[4];
                ldsm4(r, sKh + boff + kb + (uint32_t)((warp_n + p*16) * ROWB));
                bfrag[p*2][0] = r[0]; bfrag[p*2][1] = r[1];
                bfrag[p*2+1][0] = r[2]; bfrag[p*2+1][1] = r[3];
            }
            #pragma unroll
            for (int i = 0; i < 4; ++i)
                #pragma unroll
                for (int j = 0; j < 4; ++j)
                    mma_bf16(acc[i][j], afrag[i], bfrag[j]);
        }
        __syncthreads();
    }

    const float scale = 0.08838834764831843f;  // 1/sqrt(128)
    float* Pout = P + (size_t)bh * Sn * Sn;
    #pragma unroll
    for (int i = 0; i < 4; ++i) {
        const int s0 = rowStart + warp_m + i * 16 + (lane >> 2);
        #pragma unroll
        for (int half = 0; half < 2; ++half) {
            const int s = s0 + half * 8;
            #pragma unroll
            for (int j = 0; j < 4; ++j) {
                const int t0 = colStart + warp_n + j * 8 + (lane & 3) * 2;
                *(float2*)&Pout[(size_t)s * Sn + t0] =
                    make_float2(acc[i][j][half*2] * scale, acc[i][j][half*2+1] * scale);
            }
        }
    }
}

// ============================================================================
// Softmax: mask by index (t<=s), write split-bf16 probs.
// ============================================================================
__global__ void __launch_bounds__(128)
softmax_kernel(const float* __restrict__ P, __nv_bfloat16* __restrict__ PH,
               __nv_bfloat16* __restrict__ PL)
{
    const size_t row = blockIdx.x;
    const float* p = P + row * Sn;
    const int s = (int)(row & (Sn - 1));
    const int tid = threadIdx.x;
    float4 v = ((const float4*)p)[tid];
    const int t0 = tid * 4;
    v.x = (t0     <= s) ? v.x : -1e9f;
    v.y = (t0 + 1 <= s) ? v.y : -1e9f;
    v.z = (t0 + 2 <= s) ? v.z : -1e9f;
    v.w = (t0 + 3 <= s) ? v.w : -1e9f;

    float mx = fmaxf(fmaxf(v.x, v.y), fmaxf(v.z, v.w));
    #pragma unroll
    for (int o = 16; o; o >>= 1) mx = fmaxf(mx, __shfl_xor_sync(0xffffffffu, mx, o));
    __shared__ float red[4];
    if ((tid & 31) == 0) red[tid >> 5] = mx;
    __syncthreads();
    mx = fmaxf(fmaxf(red[0], red[1]), fmaxf(red[2], red[3]));

    float e0 = expf(v.x - mx), e1 = expf(v.y - mx);
    float e2 = expf(v.z - mx), e3 = expf(v.w - mx);
    float sm = e0 + e1 + e2 + e3;
    #pragma unroll
    for (int o = 16; o; o >>= 1) sm += __shfl_xor_sync(0xffffffffu, sm, o);
    __shared__ float red2[4];
    if ((tid & 31) == 0) red2[tid >> 5] = sm;
    __syncthreads();
    sm = red2[0] + red2[1] + red2[2] + red2[3];

    const float inv = 1.0f / sm;
    float p0 = e0 * inv, p1 = e1 * inv, p2 = e2 * inv, p3 = e3 * inv;

    __nv_bfloat16 h0 = __float2bfloat16(p0), h1 = __float2bfloat16(p1);
    __nv_bfloat16 h2 = __float2bfloat16(p2), h3 = __float2bfloat16(p3);
    __nv_bfloat162* PH2 = (__nv_bfloat162*)(PH + row * Sn);
    __nv_bfloat162* PL2 = (__nv_bfloat162*)(PL + row * Sn);
    PH2[tid*2]   = __halves2bfloat162(h0, h1);
    PH2[tid*2+1] = __halves2bfloat162(h2, h3);
    PL2[tid*2]   = __halves2bfloat162(
        __float2bfloat16(p0 - __bfloat162float(h0)),
        __float2bfloat16(p1 - __bfloat162float(h1)));
    PL2[tid*2+1] = __halves2bfloat162(
        __float2bfloat16(p2 - __bfloat162float(h2)),
        __float2bfloat16(p3 - __bfloat162float(h3)));
}

// ============================================================================
// AV HMMA: O = P @ V (split-3: PhVh + PhVl + PlVh); split-bf16 output for WO.
// B operand (V, [t][d] layout) loaded via ldmatrix.trans.
// ============================================================================
#define AVBUF_B  (2 * TILE_B + 2 * VTILE_B)   // Ph,Pl,Vh,Vl = 37888
#define AV_SMEM  (2 * AVBUF_B)                // 75776

__global__ void __launch_bounds__(256)
av_mma(const __nv_bfloat16* __restrict__ Ph, const __nv_bfloat16* __restrict__ Pl,
       const __nv_bfloat16* __restrict__ Vh, const __nv_bfloat16* __restrict__ Vl,
       __nv_bfloat16* __restrict__ Oh, __nv_bfloat16* __restrict__ Ol)
{
    extern __shared__ char smem_raw[];
    const uint32_t sb = smem_u32(smem_raw);

    const int bh = blockIdx.z;
    const int b = bh >> 4, h = bh & 15;
    const int rowStart = blockIdx.y * 128;   // s tile
    const int tid  = threadIdx.x;
    const int wid  = tid >> 5;
    const int lane = tid & 31;
    const int warp_m = (wid & 1) * 64;
    const int warp_n = (wid >> 1) * 32;

    const __nv_bfloat16* gPh = Ph + (size_t)bh * Sn * Sn + (size_t)rowStart * Sn;
    const __nv_bfloat16* gPl = Pl + (size_t)bh * Sn * Sn + (size_t)rowStart * Sn;
    const __nv_bfloat16* gVh = Vh + (size_t)(b * Sn) * Dn + h * HDn;
    const __nv_bfloat16* gVl = Vl + (size_t)(b * Sn) * Dn + h * HDn;

    const uint32_t aoff  = (uint32_t)((lane & 15) * ROWB + (lane >> 4) * 16);
    // trans-B lane offset within a [k][n] tile (VROWB rows):
    const uint32_t boffT = (uint32_t)(((lane & 7) + ((lane >> 3) & 1) * 8) * VROWB
                                      + (lane >> 4) * 16);

    float acc[4][4][4];
    #pragma unroll
    for (int i = 0; i < 4; i++)
        #pragma unroll
        for (int j = 0; j < 4; j++)
            #pragma unroll
            for (int r = 0; r < 4; r++) acc[i][j][r] = 0.f;

    const int nchunk = (blockIdx.y + 1) * 4;   // causal K limit

    {
        const uint32_t bb = sb;
        load_tile (gPh, Sn, bb, tid);
        load_tile (gPl, Sn, bb + TILE_B, tid);
        load_vtile(gVh, bb + 2*TILE_B, tid);
        load_vtile(gVl, bb + 2*TILE_B + VTILE_B, tid);
        cp_commit();
    }

    #pragma unroll 1
    for (int c = 0; c < nchunk; ++c) {
        if (c + 1 < nchunk) {
            const uint32_t bb = sb + ((c + 1) & 1) * AVBUF_B;
            const int k0 = (c + 1) * KC;
            load_tile (gPh + k0, Sn, bb, tid);
            load_tile (gPl + k0, Sn, bb + TILE_B, tid);
            load_vtile(gVh + (size_t)k0 * Dn, bb + 2*TILE_B, tid);
            load_vtile(gVl + (size_t)k0 * Dn, bb + 2*TILE_B + VTILE_B, tid);
            cp_commit();
            cp_wait<1>();
        } else {
            cp_wait<0>();
        }
        __syncthreads();

        const uint32_t bb  = sb + (c & 1) * AVBUF_B;
        const uint32_t sPh = bb,            sPl = bb + TILE_B;
        const uint32_t sVh = bb + 2*TILE_B, sVl = bb + 2*TILE_B + VTILE_B;

        #pragma unroll
        for (int kk = 0; kk < 2; ++kk) {
            const uint32_t kbA = (uint32_t)(kk * 32);          // A: 16 bf16 = 32 B
            const uint32_t kbB = (uint32_t)(kk * 16 * VROWB);  // B: 16 k-rows
            uint32_t afrag[4][4], bfrag[4][2];

            #pragma unroll
            for (int i = 0; i < 4; ++i)
                ldsm4(afrag[i], sPh + aoff + kbA + (uint32_t)((warp_m + i*16) * ROWB));
            #pragma unroll
            for (int g = 0; g < 2; ++g) {
                uint32_t r[4];
                ldsm4t(r, sVh + boffT + kbB + (uint32_t)((warp_n + g*16) * 2));
                bfrag[g*2][0] = r[0]; bfrag[g*2][1] = r[1];
                bfrag[g*2+1][0] = r[2]; bfrag[g*2+1][1] = r[3];
            }
            #pragma unroll
            for (int i = 0; i < 4; ++i)
                #pragma unroll
                for (int j = 0; j < 4; ++j)
                    mma_bf16(acc[i][j], afrag[i], bfrag[j]);

            #pragma unroll
            for (int g = 0; g < 2; ++g) {
                uint32_t r[4];
                ldsm4t(r, sVl + boffT + kbB + (uint32_t)((warp_n + g*16) * 2));
                bfrag[g*2][0] = r[0]; bfrag[g*2][1] = r[1];
                bfrag[g*2+1][0] = r[2]; bfrag[g*2+1][1] = r[3];
            }
            #pragma unroll
            for (int i = 0; i < 4; ++i)
                #pragma unroll
                for (int j = 0; j < 4; ++j)
                    mma_bf16(acc[i][j], afrag[i], bfrag[j]);

            #pragma unroll
            for (int i = 0; i < 4; ++i)
                ldsm4(afrag[i], sPl + aoff + kbA + (uint32_t)((warp_m + i*16) * ROWB));
            #pragma unroll
            for (int g = 0; g < 2; ++g) {
                uint32_t r[4];
                ldsm4t(r, sVh + boffT + kbB + (uint32_t)((warp_n + g*16) * 2));
                bfrag[g*2][0] = r[0]; bfrag[g*2][1] = r[1];
                bfrag[g*2+1][0] = r[2]; bfrag[g*2+1][1] = r[3];
            }
            #pragma unroll
            for (int i = 0; i < 4; ++i)
                #pragma unroll
                for (int j = 0; j < 4; ++j)
                    mma_bf16(acc[i][j], afrag[i], bfrag[j]);
        }
        __syncthreads();
    }

    // ---- epilogue: split-bf16 store into WO-GEMM A layout ----
    #pragma unroll
    for (int i = 0; i < 4; ++i) {
        const int s0 = rowStart + warp_m + i * 16 + (lane >> 2);
        #pragma unroll
        for (int half = 0; half < 2; ++half) {
            const int s = s0 + half * 8;
            const size_t rbase = ((size_t)(b * Sn + s)) * Dn + h * HDn;
            #pragma unroll
            for (int j = 0; j < 4; ++j) {
                const int c0 = warp_n + j * 8 + (lane & 3) * 2;
                split_store(Oh, Ol, rbase + c0, acc[i][j][half*2], acc[i][j][half*2+1]);
            }
        }
    }
}

// ============================================================================
extern "C" void kernel_launch(void* const* d_in, const int* in_sizes, int n_in,
                              void* d_out, int out_size)
{
    const float* x  = (const float*)d_in[0];
    const float* wq = (const float*)d_in[2];
    const float* bq = (const float*)d_in[3];
    const float* wk = (const float*)d_in[4];
    const float* bk = (const float*)d_in[5];
    const float* wv = (const float*)d_in[6];
    const float* bv = (const float*)d_in[7];
    const float* wo = (const float*)d_in[8];
    const float* bo = (const float*)d_in[9];
    float* out = (float*)d_out;

    float* pp;
    __nv_bfloat16 *ahi, *alo, *whi, *wlo, *qh, *ql, *kh, *kl, *vh, *vl, *ph, *pl;
    cudaGetSymbolAddress((void**)&pp, g_p);
    cudaGetSymbolAddress((void**)&ahi, g_ahi);
    cudaGetSymbolAddress((void**)&alo, g_alo);
    cudaGetSymbolAddress((void**)&whi, g_whi);
    cudaGetSymbolAddress((void**)&wlo, g_wlo);
    cudaGetSymbolAddress((void**)&qh, g_qh);
    cudaGetSymbolAddress((void**)&ql, g_ql);
    cudaGetSymbolAddress((void**)&kh, g_kh);
    cudaGetSymbolAddress((void**)&kl, g_kl);
    cudaGetSymbolAddress((void**)&vh, g_vh);
    cudaGetSymbolAddress((void**)&vl, g_vl);
    cudaGetSymbolAddress((void**)&ph, g_ph);
    cudaGetSymbolAddress((void**)&pl, g_pl);

    cudaFuncSetAttribute(gemm_mma<0>, cudaFuncAttributeMaxDynamicSharedMemorySize, GEMM_SMEM);
    cudaFuncSetAttribute(gemm_mma<1>, cudaFuncAttributeMaxDynamicSharedMemorySize, GEMM_SMEM);
    cudaFuncSetAttribute(gemm_mma<2>, cudaFuncAttributeMaxDynamicSharedMemorySize, GEMM_SMEM);
    cudaFuncSetAttribute(logits_mma, cudaFuncAttributeMaxDynamicSharedMemorySize, LOGIT_SMEM);
    cudaFuncSetAttribute(av_mma, cudaFuncAttributeMaxDynamicSharedMemorySize, AV_SMEM);

    const int nSplitBlks = (int)(((size_t)Mtot * Dn / 4) / 256);
    dim3 gT(Dn / 32, Dn / 32), bT(32, 8);
    dim3 gG(Dn / 128, Mtot / 128);   // (16, 64)

    split_kernel<<<nSplitBlks, 256>>>((const float4*)x, ahi, alo);

    splitT_kernel<<<gT, bT>>>(wq, whi, wlo);
    gemm_mma<1><<<gG, 256, GEMM_SMEM>>>(ahi, alo, whi, wlo, bq, nullptr, qh, ql);

    splitT_kernel<<<gT, bT>>>(wk, whi, wlo);
    gemm_mma<1><<<gG, 256, GEMM_SMEM>>>(ahi, alo, whi, wlo, bk, nullptr, kh, kl);

    splitT_kernel<<<gT, bT>>>(wv, whi, wlo);
    gemm_mma<2><<<gG, 256, GEMM_SMEM>>>(ahi, alo, whi, wlo, bv, nullptr, vh, vl);

    dim3 glog(Sn / 128, Sn / 128, Bn * Hn);    // (4, 4, 256)
    logits_mma<<<glog, 256, LOGIT_SMEM>>>(qh, ql, kh, kl, pp);

    softmax_kernel<<<Bn * Hn * Sn, 128>>>(pp, ph, pl);

    dim3 gav(1, Sn / 128, Bn * Hn);            // (1, 4, 256)
    av_mma<<<gav, 256, AV_SMEM>>>(ph, pl, vh, vl, ahi, alo);

    splitT_kernel<<<gT, bT>>>(wo, whi, wlo);
    gemm_mma<0><<<gG, 256, GEMM_SMEM>>>(ahi, alo, whi, wlo, bo, out, nullptr, nullptr);
}